// round 2
// baseline (speedup 1.0000x reference)
#include <cuda_runtime.h>
#include <math.h>

#define N_MAX 100000
#define E_MAX 3200000
#define SCAN_TPB 512
#define SCAN_NB ((N_MAX + SCAN_TPB - 1) / SCAN_TPB)

// ---- device scratch (static globals: allocation-free rule) ----
__device__ int    g_deg[N_MAX];
__device__ int    g_off[N_MAX + 1];
__device__ int    g_cur[N_MAX];
__device__ float  g_dinv[N_MAX];
__device__ int    g_srcs[E_MAX];
__device__ float4 g_bufA[N_MAX * 16];   // 64 floats/row max
__device__ float4 g_bufB[N_MAX * 16];
__device__ int    g_bsum[SCAN_NB];

// ---------------- CSR build ----------------
__global__ void k_zero(int n) {
    int i = blockIdx.x * blockDim.x + threadIdx.x;
    if (i < n) g_deg[i] = 0;
}

__global__ void k_count(const int* __restrict__ ei, int E) {
    int e = blockIdx.x * blockDim.x + threadIdx.x;
    if (e < E) atomicAdd(&g_deg[ei[E + e]], 1);
}

__global__ void k_scan1(int n) {
    __shared__ int sd[SCAN_TPB];
    int t = threadIdx.x;
    int i = blockIdx.x * SCAN_TPB + t;
    int v = (i < n) ? g_deg[i] : 0;
    sd[t] = v;
    __syncthreads();
    for (int off = 1; off < SCAN_TPB; off <<= 1) {
        int x = (t >= off) ? sd[t - off] : 0;
        __syncthreads();
        sd[t] += x;
        __syncthreads();
    }
    if (i < n) g_off[i] = sd[t] - v;              // exclusive within block
    if (t == SCAN_TPB - 1) g_bsum[blockIdx.x] = sd[t];
}

__global__ void k_scan2(int nb) {
    __shared__ int sd[256];
    int t = threadIdx.x;
    int v = (t < nb) ? g_bsum[t] : 0;
    sd[t] = v;
    __syncthreads();
    for (int off = 1; off < 256; off <<= 1) {
        int x = (t >= off) ? sd[t - off] : 0;
        __syncthreads();
        sd[t] += x;
        __syncthreads();
    }
    if (t < nb) g_bsum[t] = sd[t] - v;            // exclusive block prefix
}

__global__ void k_scan3(int n, int E) {
    int i = blockIdx.x * blockDim.x + threadIdx.x;
    if (i < n) {
        int off = g_off[i] + g_bsum[i / SCAN_TPB];
        g_off[i] = off;
        g_cur[i] = off;
        g_dinv[i] = rsqrtf((float)(g_deg[i] + 1));  // +1: self loop
        if (i == 0) g_off[n] = E;
    }
}

__global__ void k_fill(const int* __restrict__ ei, int E) {
    int e = blockIdx.x * blockDim.x + threadIdx.x;
    if (e < E) {
        int s = ei[e];
        int d = ei[E + e];
        int p = atomicAdd(&g_cur[d], 1);
        g_srcs[p] = s;
    }
}

// ---------------- layer 1 transform: T1 = x*dinv * W1 (1->16), bufA stride 4 ----------------
__global__ void k_node1(const float* __restrict__ x, const float* __restrict__ W1, int n) {
    int v = blockIdx.x * blockDim.x + threadIdx.x;
    if (v >= n) return;
    float s = x[v] * g_dinv[v];
    const float4* w = (const float4*)W1;
#pragma unroll
    for (int j = 0; j < 4; j++) {
        float4 ww = w[j];
        g_bufA[v * 4 + j] = make_float4(s * ww.x, s * ww.y, s * ww.z, s * ww.w);
    }
}

// ---------------- gather-aggregate: bufA -> bufB, Y = relu(agg*dinv + b) ----------------
// C float4-chunks per row; group of C threads per node, lane c owns chunk c.
template <int C>
__global__ void k_agg(const float* __restrict__ b, int n) {
    int gid = blockIdx.x * blockDim.x + threadIdx.x;
    int v = gid / C;
    int c = gid % C;
    if (v >= n) return;
    float4 acc = g_bufA[v * C + c];               // self-loop term
    int e = g_off[v];
    int e1 = g_off[v + 1];
#pragma unroll 4
    for (; e < e1; e++) {
        int s = __ldg(&g_srcs[e]);                // same addr across group: L1 broadcast
        float4 t = __ldg(&g_bufA[s * C + c]);
        acc.x += t.x; acc.y += t.y; acc.z += t.z; acc.w += t.w;
    }
    float dv = g_dinv[v];
    float4 bb = ((const float4*)b)[c];
    float4 o;
    o.x = fmaxf(fmaf(acc.x, dv, bb.x), 0.0f);
    o.y = fmaxf(fmaf(acc.y, dv, bb.y), 0.0f);
    o.z = fmaxf(fmaf(acc.z, dv, bb.z), 0.0f);
    o.w = fmaxf(fmaf(acc.w, dv, bb.w), 0.0f);
    g_bufB[v * C + c] = o;
}

// ---------------- node transform 16->64: bufB(stride4) -> bufA(stride16) ----------------
__global__ void k_node2(const float* __restrict__ W2, int n) {
    __shared__ float sW[16 * 64];
    int t = threadIdx.x;
    for (int i = t; i < 16 * 64; i += blockDim.x) sW[i] = W2[i];
    __syncthreads();
    int v = blockIdx.x * blockDim.x + t;
    if (v >= n) return;
    float dv = g_dinv[v];
    float y[16];
#pragma unroll
    for (int j = 0; j < 4; j++) {
        float4 yy = g_bufB[v * 4 + j];
        y[4 * j + 0] = yy.x * dv; y[4 * j + 1] = yy.y * dv;
        y[4 * j + 2] = yy.z * dv; y[4 * j + 3] = yy.w * dv;
    }
    float4 acc[16];
#pragma unroll
    for (int j = 0; j < 16; j++) acc[j] = make_float4(0.f, 0.f, 0.f, 0.f);
#pragma unroll
    for (int i = 0; i < 16; i++) {
        float yi = y[i];
        const float4* wr = (const float4*)&sW[i * 64];
#pragma unroll
        for (int j = 0; j < 16; j++) {
            float4 w = wr[j];
            acc[j].x = fmaf(yi, w.x, acc[j].x);
            acc[j].y = fmaf(yi, w.y, acc[j].y);
            acc[j].z = fmaf(yi, w.z, acc[j].z);
            acc[j].w = fmaf(yi, w.w, acc[j].w);
        }
    }
#pragma unroll
    for (int j = 0; j < 16; j++) g_bufA[v * 16 + j] = acc[j];
}

// ---------------- node transform 64->64: bufB(stride16) -> bufA(stride16) ----------------
__global__ void k_node3(const float* __restrict__ W3, int n) {
    __shared__ float sW[64 * 64];                 // 16 KB
    int t = threadIdx.x;
    for (int i = t; i < 64 * 64; i += blockDim.x) sW[i] = W3[i];
    __syncthreads();
    int v = blockIdx.x * blockDim.x + t;
    if (v >= n) return;
    float dv = g_dinv[v];
    float4 acc[16];
#pragma unroll
    for (int j = 0; j < 16; j++) acc[j] = make_float4(0.f, 0.f, 0.f, 0.f);
#pragma unroll
    for (int i4 = 0; i4 < 16; i4++) {
        float4 yy = g_bufB[v * 16 + i4];
        yy.x *= dv; yy.y *= dv; yy.z *= dv; yy.w *= dv;
        const float4* w0 = (const float4*)&sW[(4 * i4 + 0) * 64];
        const float4* w1 = (const float4*)&sW[(4 * i4 + 1) * 64];
        const float4* w2 = (const float4*)&sW[(4 * i4 + 2) * 64];
        const float4* w3 = (const float4*)&sW[(4 * i4 + 3) * 64];
#pragma unroll
        for (int j = 0; j < 16; j++) {
            float4 a = acc[j];
            float4 ww;
            ww = w0[j]; a.x = fmaf(yy.x, ww.x, a.x); a.y = fmaf(yy.x, ww.y, a.y); a.z = fmaf(yy.x, ww.z, a.z); a.w = fmaf(yy.x, ww.w, a.w);
            ww = w1[j]; a.x = fmaf(yy.y, ww.x, a.x); a.y = fmaf(yy.y, ww.y, a.y); a.z = fmaf(yy.y, ww.z, a.z); a.w = fmaf(yy.y, ww.w, a.w);
            ww = w2[j]; a.x = fmaf(yy.z, ww.x, a.x); a.y = fmaf(yy.z, ww.y, a.y); a.z = fmaf(yy.z, ww.z, a.z); a.w = fmaf(yy.z, ww.w, a.w);
            ww = w3[j]; a.x = fmaf(yy.w, ww.x, a.x); a.y = fmaf(yy.w, ww.y, a.y); a.z = fmaf(yy.w, ww.z, a.z); a.w = fmaf(yy.w, ww.w, a.w);
            acc[j] = a;
        }
    }
#pragma unroll
    for (int j = 0; j < 16; j++) g_bufA[v * 16 + j] = acc[j];
}

// ---------------- node transform 64->5 (pad to 8): bufB(stride16) -> bufA(stride2) ----------------
__global__ void k_node4(const float* __restrict__ W4, int n) {
    __shared__ float sW[64 * 5];
    int t = threadIdx.x;
    for (int i = t; i < 64 * 5; i += blockDim.x) sW[i] = W4[i];
    __syncthreads();
    int v = blockIdx.x * blockDim.x + t;
    if (v >= n) return;
    float dv = g_dinv[v];
    float acc[5] = {0.f, 0.f, 0.f, 0.f, 0.f};
#pragma unroll
    for (int i4 = 0; i4 < 16; i4++) {
        float4 yy = g_bufB[v * 16 + i4];
        const float* w0 = &sW[(4 * i4 + 0) * 5];
        const float* w1 = &sW[(4 * i4 + 1) * 5];
        const float* w2 = &sW[(4 * i4 + 2) * 5];
        const float* w3 = &sW[(4 * i4 + 3) * 5];
#pragma unroll
        for (int j = 0; j < 5; j++) {
            acc[j] = fmaf(yy.x, w0[j], acc[j]);
            acc[j] = fmaf(yy.y, w1[j], acc[j]);
            acc[j] = fmaf(yy.z, w2[j], acc[j]);
            acc[j] = fmaf(yy.w, w3[j], acc[j]);
        }
    }
    g_bufA[v * 2 + 0] = make_float4(dv * acc[0], dv * acc[1], dv * acc[2], dv * acc[3]);
    g_bufA[v * 2 + 1] = make_float4(dv * acc[4], 0.f, 0.f, 0.f);
}

// ---------------- final aggregate (d=5, padded 8) + bias + log_softmax ----------------
__global__ void k_final(const float* __restrict__ b4, float* __restrict__ out, int n) {
    int v = blockIdx.x * blockDim.x + threadIdx.x;
    if (v >= n) return;
    float4 a0 = g_bufA[v * 2 + 0];
    float4 a1 = g_bufA[v * 2 + 1];
    int e = g_off[v];
    int e1 = g_off[v + 1];
#pragma unroll 4
    for (; e < e1; e++) {
        int s = __ldg(&g_srcs[e]);
        float4 t0 = __ldg(&g_bufA[s * 2 + 0]);
        float4 t1 = __ldg(&g_bufA[s * 2 + 1]);
        a0.x += t0.x; a0.y += t0.y; a0.z += t0.z; a0.w += t0.w;
        a1.x += t1.x;
    }
    float dv = g_dinv[v];
    float z[5];
    z[0] = fmaf(a0.x, dv, b4[0]);
    z[1] = fmaf(a0.y, dv, b4[1]);
    z[2] = fmaf(a0.z, dv, b4[2]);
    z[3] = fmaf(a0.w, dv, b4[3]);
    z[4] = fmaf(a1.x, dv, b4[4]);
    float m = z[0];
#pragma unroll
    for (int j = 1; j < 5; j++) m = fmaxf(m, z[j]);
    float sum = 0.f;
#pragma unroll
    for (int j = 0; j < 5; j++) sum += expf(z[j] - m);
    float l = m + logf(sum);
#pragma unroll
    for (int j = 0; j < 5; j++) out[v * 5 + j] = z[j] - l;
}

extern "C" void kernel_launch(void* const* d_in, const int* in_sizes, int n_in,
                              void* d_out, int out_size) {
    const float* x  = (const float*)d_in[0];
    const int*   ei = (const int*)d_in[1];     // JAX default x64-disabled: int32!
    const float* W1 = (const float*)d_in[2];
    const float* b1 = (const float*)d_in[3];
    const float* W2 = (const float*)d_in[4];
    const float* b2 = (const float*)d_in[5];
    const float* W3 = (const float*)d_in[6];
    const float* b3 = (const float*)d_in[7];
    const float* W4 = (const float*)d_in[8];
    const float* b4 = (const float*)d_in[9];
    float* out = (float*)d_out;

    int N = in_sizes[0];          // 100000 (x is [N,1])
    int E = in_sizes[1] / 2;      // 3200000

    int nB   = (N + 255) / 256;
    int eB   = (E + 255) / 256;
    int snb  = (N + SCAN_TPB - 1) / SCAN_TPB;

    // CSR build (deg -> exclusive scan -> fill)
    k_zero<<<nB, 256>>>(N);
    k_count<<<eB, 256>>>(ei, E);
    k_scan1<<<snb, SCAN_TPB>>>(N);
    k_scan2<<<1, 256>>>(snb);
    k_scan3<<<nB, 256>>>(N, E);
    k_fill<<<eB, 256>>>(ei, E);

    // Layer 1 (1 -> 16)
    k_node1<<<nB, 256>>>(x, W1, N);
    k_agg<4><<<(N * 4 + 255) / 256, 256>>>(b1, N);
    // Layer 2 (16 -> 64)
    k_node2<<<nB, 256>>>(W2, N);
    k_agg<16><<<(N * 16 + 255) / 256, 256>>>(b2, N);
    // Layer 3 (64 -> 64)
    k_node3<<<nB, 256>>>(W3, N);
    k_agg<16><<<(N * 16 + 255) / 256, 256>>>(b3, N);
    // Layer 4 (64 -> 5) + log_softmax
    k_node4<<<nB, 256>>>(W4, N);
    k_final<<<nB, 256>>>(b4, out, N);
}

// round 3
// speedup vs baseline: 1.2145x; 1.2145x over previous
#include <cuda_runtime.h>
#include <math.h>

#define N_MAX 100000
#define E_MAX 3200000
#define SCAN_TPB 512
#define SCAN_NB ((N_MAX + SCAN_TPB - 1) / SCAN_TPB)

// ---- device scratch (allocation-free rule: static globals) ----
__device__ int    g_deg[N_MAX];
__device__ int    g_off[N_MAX + 1];
__device__ int    g_cur[N_MAX];
__device__ float  g_dinv[N_MAX];
__device__ float  g_t0[N_MAX];
__device__ int    g_srcs[E_MAX];
__device__ float4 g_bufA[N_MAX * 16];
__device__ float4 g_bufB[N_MAX * 16];
__device__ int    g_bsum[SCAN_NB];

// ---------------- CSR build ----------------
__global__ void k_zero(int n) {
    int i = blockIdx.x * blockDim.x + threadIdx.x;
    if (i < n) g_deg[i] = 0;
}

__global__ void k_count(const int* __restrict__ ei, int E) {
    int e = blockIdx.x * blockDim.x + threadIdx.x;
    if (e < E) atomicAdd(&g_deg[ei[E + e]], 1);
}

__global__ void k_scan1(int n) {
    __shared__ int sd[SCAN_TPB];
    int t = threadIdx.x;
    int i = blockIdx.x * SCAN_TPB + t;
    int v = (i < n) ? g_deg[i] : 0;
    sd[t] = v;
    __syncthreads();
    for (int off = 1; off < SCAN_TPB; off <<= 1) {
        int x = (t >= off) ? sd[t - off] : 0;
        __syncthreads();
        sd[t] += x;
        __syncthreads();
    }
    if (i < n) g_off[i] = sd[t] - v;
    if (t == SCAN_TPB - 1) g_bsum[blockIdx.x] = sd[t];
}

__global__ void k_scan2(int nb) {
    __shared__ int sd[256];
    int t = threadIdx.x;
    int v = (t < nb) ? g_bsum[t] : 0;
    sd[t] = v;
    __syncthreads();
    for (int off = 1; off < 256; off <<= 1) {
        int x = (t >= off) ? sd[t - off] : 0;
        __syncthreads();
        sd[t] += x;
        __syncthreads();
    }
    if (t < nb) g_bsum[t] = sd[t] - v;
}

// also computes dinv and t0 = x * dinv (layer-1 pre-scale)
__global__ void k_scan3(const float* __restrict__ x, int n, int E) {
    int i = blockIdx.x * blockDim.x + threadIdx.x;
    if (i < n) {
        int off = g_off[i] + g_bsum[i / SCAN_TPB];
        g_off[i] = off;
        g_cur[i] = off;
        float dv = rsqrtf((float)(g_deg[i] + 1));   // +1 self loop
        g_dinv[i] = dv;
        g_t0[i] = x[i] * dv;
        if (i == 0) g_off[n] = E;
    }
}

__global__ void k_fill(const int* __restrict__ ei, int E) {
    int e = blockIdx.x * blockDim.x + threadIdx.x;
    if (e < E) {
        int s = ei[e];
        int d = ei[E + e];
        int p = atomicAdd(&g_cur[d], 1);
        g_srcs[p] = s;
    }
}

// ---------------- layer 1: scalar agg of t0, then h1 = relu(a*W1+b1), t1 = dinv*h1 -> bufA (d16) ----------------
__global__ void k_l1(const float* __restrict__ W1, const float* __restrict__ b1, int n) {
    __shared__ float sw[16], sb[16];
    if (threadIdx.x < 16) { sw[threadIdx.x] = W1[threadIdx.x]; sb[threadIdx.x] = b1[threadIdx.x]; }
    __syncthreads();
    int v = blockIdx.x * blockDim.x + threadIdx.x;
    if (v >= n) return;
    float a = g_t0[v];
    int e = g_off[v], e1 = g_off[v + 1];
#pragma unroll 4
    for (; e < e1; e++) a += __ldg(&g_t0[__ldg(&g_srcs[e])]);
    float dv = g_dinv[v];
    a *= dv;
#pragma unroll
    for (int j = 0; j < 4; j++) {
        float4 o;
        o.x = dv * fmaxf(fmaf(a, sw[4 * j + 0], sb[4 * j + 0]), 0.f);
        o.y = dv * fmaxf(fmaf(a, sw[4 * j + 1], sb[4 * j + 1]), 0.f);
        o.z = dv * fmaxf(fmaf(a, sw[4 * j + 2], sb[4 * j + 2]), 0.f);
        o.w = dv * fmaxf(fmaf(a, sw[4 * j + 3], sb[4 * j + 3]), 0.f);
        g_bufA[v * 4 + j] = o;
    }
}

// ---------------- pure normalized aggregate: out = dinv*(in[v] + sum in[src]), bufA -> bufB ----------------
template <int C>
__global__ void k_aggp(int n) {
    int gid = blockIdx.x * blockDim.x + threadIdx.x;
    int v = gid / C;
    int c = gid % C;
    if (v >= n) return;
    float4 acc = g_bufA[v * C + c];
    int e = g_off[v], e1 = g_off[v + 1];
#pragma unroll 4
    for (; e < e1; e++) {
        int s = __ldg(&g_srcs[e]);
        float4 t = __ldg(&g_bufA[s * C + c]);
        acc.x += t.x; acc.y += t.y; acc.z += t.z; acc.w += t.w;
    }
    float dv = g_dinv[v];
    g_bufB[v * C + c] = make_float4(acc.x * dv, acc.y * dv, acc.z * dv, acc.w * dv);
}

// ---------------- fused W2 + relu + W3 + dinv: g(d16, bufB) -> t3(d64, bufA) ----------------
__global__ __launch_bounds__(128) void k_t23(const float* __restrict__ W2,
                                             const float* __restrict__ b2,
                                             const float* __restrict__ W3, int n) {
    __shared__ float sW2[16 * 64];
    __shared__ float sW3[64 * 64];
    __shared__ float sb2[64];
    int t = threadIdx.x;
    for (int i = t; i < 16 * 64; i += blockDim.x) sW2[i] = W2[i];
    for (int i = t; i < 64 * 64; i += blockDim.x) sW3[i] = W3[i];
    if (t < 64) sb2[t] = b2[t];
    __syncthreads();
    int v = blockIdx.x * blockDim.x + t;
    if (v >= n) return;
    float g[16];
#pragma unroll
    for (int j = 0; j < 4; j++) {
        float4 gg = g_bufB[v * 4 + j];
        g[4 * j] = gg.x; g[4 * j + 1] = gg.y; g[4 * j + 2] = gg.z; g[4 * j + 3] = gg.w;
    }
    // y = relu(g W2 + b2)
    float y[64];
#pragma unroll
    for (int jj = 0; jj < 16; jj++) {
        float4 a = ((const float4*)sb2)[jj];
#pragma unroll
        for (int i = 0; i < 16; i++) {
            float4 w = ((const float4*)&sW2[i * 64])[jj];
            a.x = fmaf(g[i], w.x, a.x); a.y = fmaf(g[i], w.y, a.y);
            a.z = fmaf(g[i], w.z, a.z); a.w = fmaf(g[i], w.w, a.w);
        }
        y[4 * jj]     = fmaxf(a.x, 0.f);
        y[4 * jj + 1] = fmaxf(a.y, 0.f);
        y[4 * jj + 2] = fmaxf(a.z, 0.f);
        y[4 * jj + 3] = fmaxf(a.w, 0.f);
    }
    // t3 = dinv * (y W3), computed in two halves of 32 outputs
    float dv = g_dinv[v];
#pragma unroll
    for (int h = 0; h < 2; h++) {
        float4 z[8];
#pragma unroll
        for (int j = 0; j < 8; j++) z[j] = make_float4(0.f, 0.f, 0.f, 0.f);
#pragma unroll
        for (int i = 0; i < 64; i++) {
            float yi = y[i];
            const float4* wr = (const float4*)&sW3[i * 64 + h * 32];
#pragma unroll
            for (int j = 0; j < 8; j++) {
                float4 w = wr[j];
                z[j].x = fmaf(yi, w.x, z[j].x); z[j].y = fmaf(yi, w.y, z[j].y);
                z[j].z = fmaf(yi, w.z, z[j].z); z[j].w = fmaf(yi, w.w, z[j].w);
            }
        }
#pragma unroll
        for (int j = 0; j < 8; j++)
            g_bufA[v * 16 + h * 8 + j] = make_float4(z[j].x * dv, z[j].y * dv, z[j].z * dv, z[j].w * dv);
    }
}

// ---------------- d=64 agg + b3 + relu + W4 + group reduce + dinv: bufA -> bufB (d5 pad8) ----------------
__global__ void k_agg3w4(const float* __restrict__ b3, const float* __restrict__ W4, int n) {
    __shared__ float sW4[64 * 5];
    int t = threadIdx.x;
    for (int i = t; i < 64 * 5; i += blockDim.x) sW4[i] = W4[i];
    __syncthreads();
    int gid = blockIdx.x * blockDim.x + t;
    int v = gid / 16;
    int c = gid % 16;
    if (v >= n) return;
    float4 acc = g_bufA[v * 16 + c];
    int e = g_off[v], e1 = g_off[v + 1];
#pragma unroll 4
    for (; e < e1; e++) {
        int s = __ldg(&g_srcs[e]);
        float4 x = __ldg(&g_bufA[s * 16 + c]);
        acc.x += x.x; acc.y += x.y; acc.z += x.z; acc.w += x.w;
    }
    float dv = g_dinv[v];
    float4 bb = ((const float4*)b3)[c];
    float h0 = fmaxf(fmaf(acc.x, dv, bb.x), 0.f);
    float h1 = fmaxf(fmaf(acc.y, dv, bb.y), 0.f);
    float h2 = fmaxf(fmaf(acc.z, dv, bb.z), 0.f);
    float h3 = fmaxf(fmaf(acc.w, dv, bb.w), 0.f);
    const float* w = &sW4[c * 4 * 5];
    float p[5];
#pragma unroll
    for (int j = 0; j < 5; j++)
        p[j] = fmaf(h0, w[j], fmaf(h1, w[5 + j], fmaf(h2, w[10 + j], h3 * w[15 + j])));
    unsigned m = __activemask();
#pragma unroll
    for (int off = 8; off > 0; off >>= 1) {
#pragma unroll
        for (int j = 0; j < 5; j++) p[j] += __shfl_down_sync(m, p[j], off, 16);
    }
    if (c == 0) {
        g_bufB[v * 2 + 0] = make_float4(dv * p[0], dv * p[1], dv * p[2], dv * p[3]);
        g_bufB[v * 2 + 1] = make_float4(dv * p[4], 0.f, 0.f, 0.f);
    }
}

// ---------------- final d=5 agg + b4 + log_softmax ----------------
__global__ void k_final(const float* __restrict__ b4, float* __restrict__ out, int n) {
    int v = blockIdx.x * blockDim.x + threadIdx.x;
    if (v >= n) return;
    float4 a0 = g_bufB[v * 2 + 0];
    float4 a1 = g_bufB[v * 2 + 1];
    int e = g_off[v], e1 = g_off[v + 1];
#pragma unroll 4
    for (; e < e1; e++) {
        int s = __ldg(&g_srcs[e]);
        float4 t0 = __ldg(&g_bufB[s * 2 + 0]);
        float4 t1 = __ldg(&g_bufB[s * 2 + 1]);
        a0.x += t0.x; a0.y += t0.y; a0.z += t0.z; a0.w += t0.w;
        a1.x += t1.x;
    }
    float dv = g_dinv[v];
    float z[5];
    z[0] = fmaf(a0.x, dv, b4[0]);
    z[1] = fmaf(a0.y, dv, b4[1]);
    z[2] = fmaf(a0.z, dv, b4[2]);
    z[3] = fmaf(a0.w, dv, b4[3]);
    z[4] = fmaf(a1.x, dv, b4[4]);
    float mx = z[0];
#pragma unroll
    for (int j = 1; j < 5; j++) mx = fmaxf(mx, z[j]);
    float sum = 0.f;
#pragma unroll
    for (int j = 0; j < 5; j++) sum += expf(z[j] - mx);
    float l = mx + logf(sum);
#pragma unroll
    for (int j = 0; j < 5; j++) out[v * 5 + j] = z[j] - l;
}

extern "C" void kernel_launch(void* const* d_in, const int* in_sizes, int n_in,
                              void* d_out, int out_size) {
    const float* x  = (const float*)d_in[0];
    const int*   ei = (const int*)d_in[1];      // int32 (JAX x64 disabled)
    const float* W1 = (const float*)d_in[2];
    const float* b1 = (const float*)d_in[3];
    const float* W2 = (const float*)d_in[4];
    const float* b2 = (const float*)d_in[5];
    const float* W3 = (const float*)d_in[6];
    const float* b3 = (const float*)d_in[7];
    const float* W4 = (const float*)d_in[8];
    const float* b4 = (const float*)d_in[9];
    float* out = (float*)d_out;

    int N = in_sizes[0];
    int E = in_sizes[1] / 2;

    int nB  = (N + 255) / 256;
    int eB  = (E + 255) / 256;
    int snb = (N + SCAN_TPB - 1) / SCAN_TPB;

    // CSR build
    k_zero<<<nB, 256>>>(N);
    k_count<<<eB, 256>>>(ei, E);
    k_scan1<<<snb, SCAN_TPB>>>(N);
    k_scan2<<<1, 256>>>(snb);
    k_scan3<<<nB, 256>>>(x, N, E);
    k_fill<<<eB, 256>>>(ei, E);

    // Layer 1: scalar agg + transform (1->16)
    k_l1<<<nB, 256>>>(W1, b1, N);
    // Layer 2 agg in d=16 (before W2)
    k_aggp<4><<<(N * 4 + 255) / 256, 256>>>(N);
    // Fused W2+relu+W3 node transform
    k_t23<<<(N + 127) / 128, 128>>>(W2, b2, W3, N);
    // Layer 3 agg d=64, fused bias/relu/W4 epilogue
    k_agg3w4<<<(N * 16 + 255) / 256, 256>>>(b3, W4, N);
    // Layer 4 agg d=5 + log_softmax
    k_final<<<nB, 256>>>(b4, out, N);
}

// round 5
// speedup vs baseline: 1.2914x; 1.0633x over previous
#include <cuda_runtime.h>
#include <cuda_fp16.h>
#include <math.h>

#define N_MAX 100000
#define E_MAX 3200000
#define SCAN_TPB 512
#define SCAN_NB ((N_MAX + SCAN_TPB - 1) / SCAN_TPB)

// ---- device scratch (allocation-free rule: static globals) ----
__device__ int     g_deg[N_MAX];
__device__ int     g_off[N_MAX + 1];
__device__ int     g_cur[N_MAX];
__device__ float   g_dinv[N_MAX];
__device__ float   g_t0[N_MAX];
__device__ int     g_srcs[E_MAX];
__device__ float4  g_bufA[N_MAX * 16];      // fp32 buffers (d16 stage, d5 stage)
__device__ float4  g_bufB[N_MAX * 16];
__device__ __half2 g_bufH[N_MAX * 32];      // fp16 t3 buffer: 64 halves / node (128 B/row)
__device__ int     g_bsum[SCAN_NB];

// ---------------- CSR build ----------------
__global__ void k_zero(int n) {
    int i = blockIdx.x * blockDim.x + threadIdx.x;
    if (i < n) g_deg[i] = 0;
}

__global__ void k_count(const int* __restrict__ ei, int E) {
    int e = blockIdx.x * blockDim.x + threadIdx.x;
    if (e < E) atomicAdd(&g_deg[ei[E + e]], 1);
}

__global__ void k_scan1(int n) {
    __shared__ int sd[SCAN_TPB];
    int t = threadIdx.x;
    int i = blockIdx.x * SCAN_TPB + t;
    int v = (i < n) ? g_deg[i] : 0;
    sd[t] = v;
    __syncthreads();
    for (int off = 1; off < SCAN_TPB; off <<= 1) {
        int x = (t >= off) ? sd[t - off] : 0;
        __syncthreads();
        sd[t] += x;
        __syncthreads();
    }
    if (i < n) g_off[i] = sd[t] - v;
    if (t == SCAN_TPB - 1) g_bsum[blockIdx.x] = sd[t];
}

__global__ void k_scan2(int nb) {
    __shared__ int sd[256];
    int t = threadIdx.x;
    int v = (t < nb) ? g_bsum[t] : 0;
    sd[t] = v;
    __syncthreads();
    for (int off = 1; off < 256; off <<= 1) {
        int x = (t >= off) ? sd[t - off] : 0;
        __syncthreads();
        sd[t] += x;
        __syncthreads();
    }
    if (t < nb) g_bsum[t] = sd[t] - v;
}

// also computes dinv and t0 = x * dinv (layer-1 pre-scale)
__global__ void k_scan3(const float* __restrict__ x, int n, int E) {
    int i = blockIdx.x * blockDim.x + threadIdx.x;
    if (i < n) {
        int off = g_off[i] + g_bsum[i / SCAN_TPB];
        g_off[i] = off;
        g_cur[i] = off;
        float dv = rsqrtf((float)(g_deg[i] + 1));   // +1 self loop
        g_dinv[i] = dv;
        g_t0[i] = x[i] * dv;
        if (i == 0) g_off[n] = E;
    }
}

__global__ void k_fill(const int* __restrict__ ei, int E) {
    int e = blockIdx.x * blockDim.x + threadIdx.x;
    if (e < E) {
        int s = ei[e];
        int d = ei[E + e];
        int p = atomicAdd(&g_cur[d], 1);
        g_srcs[p] = s;
    }
}

// ---------------- layer 1: scalar agg of t0, then h1 = relu(a*W1+b1), t1 = dinv*h1 -> bufA (d16) ----------------
__global__ void k_l1(const float* __restrict__ W1, const float* __restrict__ b1, int n) {
    __shared__ float sw[16], sb[16];
    if (threadIdx.x < 16) { sw[threadIdx.x] = W1[threadIdx.x]; sb[threadIdx.x] = b1[threadIdx.x]; }
    __syncthreads();
    int v = blockIdx.x * blockDim.x + threadIdx.x;
    if (v >= n) return;
    float a = g_t0[v];
    int e = g_off[v], e1 = g_off[v + 1];
#pragma unroll 4
    for (; e < e1; e++) a += __ldg(&g_t0[__ldg(&g_srcs[e])]);
    float dv = g_dinv[v];
    a *= dv;
#pragma unroll
    for (int j = 0; j < 4; j++) {
        float4 o;
        o.x = dv * fmaxf(fmaf(a, sw[4 * j + 0], sb[4 * j + 0]), 0.f);
        o.y = dv * fmaxf(fmaf(a, sw[4 * j + 1], sb[4 * j + 1]), 0.f);
        o.z = dv * fmaxf(fmaf(a, sw[4 * j + 2], sb[4 * j + 2]), 0.f);
        o.w = dv * fmaxf(fmaf(a, sw[4 * j + 3], sb[4 * j + 3]), 0.f);
        g_bufA[v * 4 + j] = o;
    }
}

// ---------------- pure normalized aggregate d16: out = dinv*(in[v] + sum in[src]), bufA -> bufB ----------------
__global__ void k_aggp4(int n) {
    int gid = blockIdx.x * blockDim.x + threadIdx.x;
    int v = gid / 4;
    int c = gid % 4;
    if (v >= n) return;
    float4 acc = g_bufA[v * 4 + c];
    int e = g_off[v], e1 = g_off[v + 1];
#pragma unroll 4
    for (; e < e1; e++) {
        int s = __ldg(&g_srcs[e]);
        float4 t = __ldg(&g_bufA[s * 4 + c]);
        acc.x += t.x; acc.y += t.y; acc.z += t.z; acc.w += t.w;
    }
    float dv = g_dinv[v];
    g_bufB[v * 4 + c] = make_float4(acc.x * dv, acc.y * dv, acc.z * dv, acc.w * dv);
}

// ---------------- fused W2 + relu + W3 + dinv: g(d16, bufB) -> t3(d64, fp16 bufH) ----------------
__global__ __launch_bounds__(128) void k_t23(const float* __restrict__ W2,
                                             const float* __restrict__ b2,
                                             const float* __restrict__ W3, int n) {
    __shared__ float sW2[16 * 64];
    __shared__ float sW3[64 * 64];
    __shared__ float sb2[64];
    int t = threadIdx.x;
    for (int i = t; i < 16 * 64; i += blockDim.x) sW2[i] = W2[i];
    for (int i = t; i < 64 * 64; i += blockDim.x) sW3[i] = W3[i];
    if (t < 64) sb2[t] = b2[t];
    __syncthreads();
    int v = blockIdx.x * blockDim.x + t;
    if (v >= n) return;
    float g[16];
#pragma unroll
    for (int j = 0; j < 4; j++) {
        float4 gg = g_bufB[v * 4 + j];
        g[4 * j] = gg.x; g[4 * j + 1] = gg.y; g[4 * j + 2] = gg.z; g[4 * j + 3] = gg.w;
    }
    // y = relu(g W2 + b2)
    float y[64];
#pragma unroll
    for (int jj = 0; jj < 16; jj++) {
        float4 a = ((const float4*)sb2)[jj];
#pragma unroll
        for (int i = 0; i < 16; i++) {
            float4 w = ((const float4*)&sW2[i * 64])[jj];
            a.x = fmaf(g[i], w.x, a.x); a.y = fmaf(g[i], w.y, a.y);
            a.z = fmaf(g[i], w.z, a.z); a.w = fmaf(g[i], w.w, a.w);
        }
        y[4 * jj]     = fmaxf(a.x, 0.f);
        y[4 * jj + 1] = fmaxf(a.y, 0.f);
        y[4 * jj + 2] = fmaxf(a.z, 0.f);
        y[4 * jj + 3] = fmaxf(a.w, 0.f);
    }
    // t3 = dinv * (y W3), two halves of 32 outputs, stored fp16
    float dv = g_dinv[v];
#pragma unroll
    for (int h = 0; h < 2; h++) {
        float4 z[8];
#pragma unroll
        for (int j = 0; j < 8; j++) z[j] = make_float4(0.f, 0.f, 0.f, 0.f);
#pragma unroll
        for (int i = 0; i < 64; i++) {
            float yi = y[i];
            const float4* wr = (const float4*)&sW3[i * 64 + h * 32];
#pragma unroll
            for (int j = 0; j < 8; j++) {
                float4 w = wr[j];
                z[j].x = fmaf(yi, w.x, z[j].x); z[j].y = fmaf(yi, w.y, z[j].y);
                z[j].z = fmaf(yi, w.z, z[j].z); z[j].w = fmaf(yi, w.w, z[j].w);
            }
        }
#pragma unroll
        for (int j = 0; j < 8; j++) {
            g_bufH[v * 32 + h * 16 + j * 2 + 0] =
                __float22half2_rn(make_float2(z[j].x * dv, z[j].y * dv));
            g_bufH[v * 32 + h * 16 + j * 2 + 1] =
                __float22half2_rn(make_float2(z[j].z * dv, z[j].w * dv));
        }
    }
}

// ---------------- d=64 fp16 agg + b3 + relu + W4 + group reduce + dinv: bufH -> bufB (d5 pad8) ----------------
// 8 lanes per node; lane c owns halves [8c, 8c+8) = one uint4 (16 B).
__global__ void k_agg3w4(const float* __restrict__ b3, const float* __restrict__ W4, int n) {
    __shared__ float sW4[64 * 5];
    int t = threadIdx.x;
    for (int i = t; i < 64 * 5; i += blockDim.x) sW4[i] = W4[i];
    __syncthreads();
    int gid = blockIdx.x * blockDim.x + t;
    int v = gid / 8;
    int c = gid % 8;
    if (v >= n) return;

    const uint4* hp = (const uint4*)g_bufH;   // 8 uint4 per node row
    float acc[8];
    {
        uint4 hv = hp[v * 8 + c];             // self-loop term
        float2 f0 = __half22float2(*(const __half2*)&hv.x);
        float2 f1 = __half22float2(*(const __half2*)&hv.y);
        float2 f2 = __half22float2(*(const __half2*)&hv.z);
        float2 f3 = __half22float2(*(const __half2*)&hv.w);
        acc[0] = f0.x; acc[1] = f0.y; acc[2] = f1.x; acc[3] = f1.y;
        acc[4] = f2.x; acc[5] = f2.y; acc[6] = f3.x; acc[7] = f3.y;
    }
    int e = g_off[v], e1 = g_off[v + 1];
#pragma unroll 4
    for (; e < e1; e++) {
        int s = __ldg(&g_srcs[e]);
        uint4 hv = __ldg(&hp[s * 8 + c]);
        float2 f0 = __half22float2(*(const __half2*)&hv.x);
        float2 f1 = __half22float2(*(const __half2*)&hv.y);
        float2 f2 = __half22float2(*(const __half2*)&hv.z);
        float2 f3 = __half22float2(*(const __half2*)&hv.w);
        acc[0] += f0.x; acc[1] += f0.y; acc[2] += f1.x; acc[3] += f1.y;
        acc[4] += f2.x; acc[5] += f2.y; acc[6] += f3.x; acc[7] += f3.y;
    }
    float dv = g_dinv[v];
    float4 bb0 = ((const float4*)b3)[2 * c];
    float4 bb1 = ((const float4*)b3)[2 * c + 1];
    float h[8];
    h[0] = fmaxf(fmaf(acc[0], dv, bb0.x), 0.f);
    h[1] = fmaxf(fmaf(acc[1], dv, bb0.y), 0.f);
    h[2] = fmaxf(fmaf(acc[2], dv, bb0.z), 0.f);
    h[3] = fmaxf(fmaf(acc[3], dv, bb0.w), 0.f);
    h[4] = fmaxf(fmaf(acc[4], dv, bb1.x), 0.f);
    h[5] = fmaxf(fmaf(acc[5], dv, bb1.y), 0.f);
    h[6] = fmaxf(fmaf(acc[6], dv, bb1.z), 0.f);
    h[7] = fmaxf(fmaf(acc[7], dv, bb1.w), 0.f);
    const float* w = &sW4[c * 8 * 5];
    float p[5];
#pragma unroll
    for (int j = 0; j < 5; j++) {
        float s = h[0] * w[j];
#pragma unroll
        for (int i = 1; i < 8; i++) s = fmaf(h[i], w[i * 5 + j], s);
        p[j] = s;
    }
    unsigned m = __activemask();
#pragma unroll
    for (int off = 4; off > 0; off >>= 1) {
#pragma unroll
        for (int j = 0; j < 5; j++) p[j] += __shfl_down_sync(m, p[j], off, 8);
    }
    if (c == 0) {
        g_bufB[v * 2 + 0] = make_float4(dv * p[0], dv * p[1], dv * p[2], dv * p[3]);
        g_bufB[v * 2 + 1] = make_float4(dv * p[4], 0.f, 0.f, 0.f);
    }
}

// ---------------- final d=5 agg + b4 + log_softmax ----------------
__global__ void k_final(const float* __restrict__ b4, float* __restrict__ out, int n) {
    int v = blockIdx.x * blockDim.x + threadIdx.x;
    if (v >= n) return;
    float4 a0 = g_bufB[v * 2 + 0];
    float4 a1 = g_bufB[v * 2 + 1];
    int e = g_off[v], e1 = g_off[v + 1];
#pragma unroll 4
    for (; e < e1; e++) {
        int s = __ldg(&g_srcs[e]);
        float4 t0 = __ldg(&g_bufB[s * 2 + 0]);
        float4 t1 = __ldg(&g_bufB[s * 2 + 1]);
        a0.x += t0.x; a0.y += t0.y; a0.z += t0.z; a0.w += t0.w;
        a1.x += t1.x;
    }
    float dv = g_dinv[v];
    float z[5];
    z[0] = fmaf(a0.x, dv, b4[0]);
    z[1] = fmaf(a0.y, dv, b4[1]);
    z[2] = fmaf(a0.z, dv, b4[2]);
    z[3] = fmaf(a0.w, dv, b4[3]);
    z[4] = fmaf(a1.x, dv, b4[4]);
    float mx = z[0];
#pragma unroll
    for (int j = 1; j < 5; j++) mx = fmaxf(mx, z[j]);
    float sum = 0.f;
#pragma unroll
    for (int j = 0; j < 5; j++) sum += expf(z[j] - mx);
    float l = mx + logf(sum);
#pragma unroll
    for (int j = 0; j < 5; j++) out[v * 5 + j] = z[j] - l;
}

extern "C" void kernel_launch(void* const* d_in, const int* in_sizes, int n_in,
                              void* d_out, int out_size) {
    const float* x  = (const float*)d_in[0];
    const int*   ei = (const int*)d_in[1];      // int32 (JAX x64 disabled)
    const float* W1 = (const float*)d_in[2];
    const float* b1 = (const float*)d_in[3];
    const float* W2 = (const float*)d_in[4];
    const float* b2 = (const float*)d_in[5];
    const float* W3 = (const float*)d_in[6];
    const float* b3 = (const float*)d_in[7];
    const float* W4 = (const float*)d_in[8];
    const float* b4 = (const float*)d_in[9];
    float* out = (float*)d_out;

    int N = in_sizes[0];
    int E = in_sizes[1] / 2;

    int nB  = (N + 255) / 256;
    int eB  = (E + 255) / 256;
    int snb = (N + SCAN_TPB - 1) / SCAN_TPB;

    // CSR build
    k_zero<<<nB, 256>>>(N);
    k_count<<<eB, 256>>>(ei, E);
    k_scan1<<<snb, SCAN_TPB>>>(N);
    k_scan2<<<1, 256>>>(snb);
    k_scan3<<<nB, 256>>>(x, N, E);
    k_fill<<<eB, 256>>>(ei, E);

    // Layer 1: scalar agg + transform (1->16)
    k_l1<<<nB, 256>>>(W1, b1, N);
    // Layer 2 agg in d=16 (before W2)
    k_aggp4<<<(N * 4 + 255) / 256, 256>>>(N);
    // Fused W2+relu+W3 node transform (fp16 output)
    k_t23<<<(N + 127) / 128, 128>>>(W2, b2, W3, N);
    // Layer 3 agg d=64 fp16, fused bias/relu/W4 epilogue
    k_agg3w4<<<(N * 8 + 255) / 256, 256>>>(b3, W4, N);
    // Layer 4 agg d=5 + log_softmax
    k_final<<<nB, 256>>>(b4, out, N);
}

// round 7
// speedup vs baseline: 1.3093x; 1.0139x over previous
#include <cuda_runtime.h>
#include <cuda_fp16.h>
#include <math.h>

#define N_MAX 100000
#define E_MAX 3200000
#define SCAN_TPB 512
#define SCAN_NB ((N_MAX + SCAN_TPB - 1) / SCAN_TPB)

// ---- device scratch (allocation-free rule: static globals) ----
__device__ int     g_deg[N_MAX];
__device__ int     g_off[N_MAX + 1];
__device__ int     g_cur[N_MAX];
__device__ float   g_dinv[N_MAX];
__device__ float   g_t0[N_MAX];
__device__ int     g_srcs[E_MAX];
__device__ __half2 g_t1[N_MAX * 8];         // fp16 t1: 16 halves/node (32 B/row)
__device__ float4  g_bufB[N_MAX * 16];      // fp32: g (d16) and t4/out stage (d5 pad8)
__device__ __half2 g_bufH[N_MAX * 32];      // fp16 t3: 64 halves/node (128 B/row)
__device__ int     g_bsum[SCAN_NB];

// ---------------- CSR build ----------------
__global__ void k_zero(int n) {
    int i = blockIdx.x * blockDim.x + threadIdx.x;
    if (i < n) g_deg[i] = 0;
}

__global__ void k_count(const int* __restrict__ ei, int E) {
    int e = blockIdx.x * blockDim.x + threadIdx.x;
    if (e < E) atomicAdd(&g_deg[ei[E + e]], 1);
}

// vectorized: 4 dsts per thread (requires E % 4 == 0)
__global__ void k_count4(const int* __restrict__ ei, int E4) {
    int e = blockIdx.x * blockDim.x + threadIdx.x;
    if (e < E4) {
        int4 d = ((const int4*)ei)[e];      // ei already offset to dst half
        atomicAdd(&g_deg[d.x], 1);
        atomicAdd(&g_deg[d.y], 1);
        atomicAdd(&g_deg[d.z], 1);
        atomicAdd(&g_deg[d.w], 1);
    }
}

__global__ void k_scan1(int n) {
    __shared__ int sd[SCAN_TPB];
    int t = threadIdx.x;
    int i = blockIdx.x * SCAN_TPB + t;
    int v = (i < n) ? g_deg[i] : 0;
    sd[t] = v;
    __syncthreads();
    for (int off = 1; off < SCAN_TPB; off <<= 1) {
        int x = (t >= off) ? sd[t - off] : 0;
        __syncthreads();
        sd[t] += x;
        __syncthreads();
    }
    if (i < n) g_off[i] = sd[t] - v;
    if (t == SCAN_TPB - 1) g_bsum[blockIdx.x] = sd[t];
}

__global__ void k_scan2(int nb) {
    __shared__ int sd[256];
    int t = threadIdx.x;
    int v = (t < nb) ? g_bsum[t] : 0;
    sd[t] = v;
    __syncthreads();
    for (int off = 1; off < 256; off <<= 1) {
        int x = (t >= off) ? sd[t - off] : 0;
        __syncthreads();
        sd[t] += x;
        __syncthreads();
    }
    if (t < nb) g_bsum[t] = sd[t] - v;
}

// also computes dinv and t0 = x * dinv (layer-1 pre-scale)
__global__ void k_scan3(const float* __restrict__ x, int n, int E) {
    int i = blockIdx.x * blockDim.x + threadIdx.x;
    if (i < n) {
        int off = g_off[i] + g_bsum[i / SCAN_TPB];
        g_off[i] = off;
        g_cur[i] = off;
        float dv = rsqrtf((float)(g_deg[i] + 1));   // +1 self loop
        g_dinv[i] = dv;
        g_t0[i] = x[i] * dv;
        if (i == 0) g_off[n] = E;
    }
}

__global__ void k_fill(const int* __restrict__ ei, int E) {
    int e = blockIdx.x * blockDim.x + threadIdx.x;
    if (e < E) {
        int s = ei[e];
        int d = ei[E + e];
        int p = atomicAdd(&g_cur[d], 1);
        g_srcs[p] = s;
    }
}

// vectorized: 4 edges per thread (requires E % 4 == 0)
__global__ void k_fill4(const int* __restrict__ ei, int E, int E4) {
    int e = blockIdx.x * blockDim.x + threadIdx.x;
    if (e < E4) {
        int4 s = ((const int4*)ei)[e];
        int4 d = ((const int4*)(ei + E))[e];
        g_srcs[atomicAdd(&g_cur[d.x], 1)] = s.x;
        g_srcs[atomicAdd(&g_cur[d.y], 1)] = s.y;
        g_srcs[atomicAdd(&g_cur[d.z], 1)] = s.z;
        g_srcs[atomicAdd(&g_cur[d.w], 1)] = s.w;
    }
}

// ---------------- layer 1: scalar agg of t0, then t1 = dinv*relu(a*W1+b1) -> fp16 ----------------
__global__ void k_l1(const float* __restrict__ W1, const float* __restrict__ b1, int n) {
    __shared__ float sw[16], sb[16];
    if (threadIdx.x < 16) { sw[threadIdx.x] = W1[threadIdx.x]; sb[threadIdx.x] = b1[threadIdx.x]; }
    __syncthreads();
    int v = blockIdx.x * blockDim.x + threadIdx.x;
    if (v >= n) return;
    float a = g_t0[v];
    int e = g_off[v], e1 = g_off[v + 1];
#pragma unroll 4
    for (; e < e1; e++) a += __ldg(&g_t0[__ldg(&g_srcs[e])]);
    float dv = g_dinv[v];
    a *= dv;
#pragma unroll
    for (int k = 0; k < 8; k++) {
        float u0 = dv * fmaxf(fmaf(a, sw[2 * k + 0], sb[2 * k + 0]), 0.f);
        float u1 = dv * fmaxf(fmaf(a, sw[2 * k + 1], sb[2 * k + 1]), 0.f);
        g_t1[v * 8 + k] = __float22half2_rn(make_float2(u0, u1));
    }
}

// ---------------- layer-2 agg d16 fp16: g = dinv*(t1[v] + sum t1[src]) -> bufB fp32 ----------------
// 2 lanes per node; lane c owns halves [8c, 8c+8) = one uint4 (16 B). Row = 32 B (full sector).
__global__ void k_agg2(int n) {
    int gid = blockIdx.x * blockDim.x + threadIdx.x;
    int v = gid >> 1;
    int c = gid & 1;
    if (v >= n) return;
    const uint4* tp = (const uint4*)g_t1;   // 2 uint4 per row
    float acc[8];
    {
        uint4 hv = tp[v * 2 + c];
        float2 f0 = __half22float2(*(const __half2*)&hv.x);
        float2 f1 = __half22float2(*(const __half2*)&hv.y);
        float2 f2 = __half22float2(*(const __half2*)&hv.z);
        float2 f3 = __half22float2(*(const __half2*)&hv.w);
        acc[0] = f0.x; acc[1] = f0.y; acc[2] = f1.x; acc[3] = f1.y;
        acc[4] = f2.x; acc[5] = f2.y; acc[6] = f3.x; acc[7] = f3.y;
    }
    int e = g_off[v], e1 = g_off[v + 1];
#pragma unroll 4
    for (; e < e1; e++) {
        int s = __ldg(&g_srcs[e]);
        uint4 hv = __ldg(&tp[s * 2 + c]);
        float2 f0 = __half22float2(*(const __half2*)&hv.x);
        float2 f1 = __half22float2(*(const __half2*)&hv.y);
        float2 f2 = __half22float2(*(const __half2*)&hv.z);
        float2 f3 = __half22float2(*(const __half2*)&hv.w);
        acc[0] += f0.x; acc[1] += f0.y; acc[2] += f1.x; acc[3] += f1.y;
        acc[4] += f2.x; acc[5] += f2.y; acc[6] += f3.x; acc[7] += f3.y;
    }
    float dv = g_dinv[v];
    g_bufB[v * 4 + c * 2 + 0] = make_float4(acc[0] * dv, acc[1] * dv, acc[2] * dv, acc[3] * dv);
    g_bufB[v * 4 + c * 2 + 1] = make_float4(acc[4] * dv, acc[5] * dv, acc[6] * dv, acc[7] * dv);
}

// ---------------- fused W2 + relu + W3 + dinv: g(d16, bufB) -> t3(d64, fp16 bufH) ----------------
__global__ __launch_bounds__(128) void k_t23(const float* __restrict__ W2,
                                             const float* __restrict__ b2,
                                             const float* __restrict__ W3, int n) {
    __shared__ float sW2[16 * 64];
    __shared__ float sW3[64 * 64];
    __shared__ float sb2[64];
    int t = threadIdx.x;
    for (int i = t; i < 16 * 64; i += blockDim.x) sW2[i] = W2[i];
    for (int i = t; i < 64 * 64; i += blockDim.x) sW3[i] = W3[i];
    if (t < 64) sb2[t] = b2[t];
    __syncthreads();
    int v = blockIdx.x * blockDim.x + t;
    if (v >= n) return;
    float g[16];
#pragma unroll
    for (int j = 0; j < 4; j++) {
        float4 gg = g_bufB[v * 4 + j];
        g[4 * j] = gg.x; g[4 * j + 1] = gg.y; g[4 * j + 2] = gg.z; g[4 * j + 3] = gg.w;
    }
    // y = relu(g W2 + b2)
    float y[64];
#pragma unroll
    for (int jj = 0; jj < 16; jj++) {
        float4 a = ((const float4*)sb2)[jj];
#pragma unroll
        for (int i = 0; i < 16; i++) {
            float4 w = ((const float4*)&sW2[i * 64])[jj];
            a.x = fmaf(g[i], w.x, a.x); a.y = fmaf(g[i], w.y, a.y);
            a.z = fmaf(g[i], w.z, a.z); a.w = fmaf(g[i], w.w, a.w);
        }
        y[4 * jj]     = fmaxf(a.x, 0.f);
        y[4 * jj + 1] = fmaxf(a.y, 0.f);
        y[4 * jj + 2] = fmaxf(a.z, 0.f);
        y[4 * jj + 3] = fmaxf(a.w, 0.f);
    }
    // t3 = dinv * (y W3), two halves of 32 outputs, stored fp16
    float dv = g_dinv[v];
#pragma unroll
    for (int h = 0; h < 2; h++) {
        float4 z[8];
#pragma unroll
        for (int j = 0; j < 8; j++) z[j] = make_float4(0.f, 0.f, 0.f, 0.f);
#pragma unroll
        for (int i = 0; i < 64; i++) {
            float yi = y[i];
            const float4* wr = (const float4*)&sW3[i * 64 + h * 32];
#pragma unroll
            for (int j = 0; j < 8; j++) {
                float4 w = wr[j];
                z[j].x = fmaf(yi, w.x, z[j].x); z[j].y = fmaf(yi, w.y, z[j].y);
                z[j].z = fmaf(yi, w.z, z[j].z); z[j].w = fmaf(yi, w.w, z[j].w);
            }
        }
#pragma unroll
        for (int j = 0; j < 8; j++) {
            g_bufH[v * 32 + h * 16 + j * 2 + 0] =
                __float22half2_rn(make_float2(z[j].x * dv, z[j].y * dv));
            g_bufH[v * 32 + h * 16 + j * 2 + 1] =
                __float22half2_rn(make_float2(z[j].z * dv, z[j].w * dv));
        }
    }
}

// ---------------- d=64 fp16 agg + b3 + relu + W4 + group reduce + dinv: bufH -> bufB (d5 pad8, fp32) ----------------
// 8 lanes per node; lane c owns halves [8c, 8c+8) = one uint4 (16 B). Row = 128 B (full line).
__global__ void k_agg3w4(const float* __restrict__ b3, const float* __restrict__ W4, int n) {
    __shared__ float sW4[64 * 5];
    int t = threadIdx.x;
    for (int i = t; i < 64 * 5; i += blockDim.x) sW4[i] = W4[i];
    __syncthreads();
    int gid = blockIdx.x * blockDim.x + t;
    int v = gid / 8;
    int c = gid % 8;
    if (v >= n) return;

    const uint4* hp = (const uint4*)g_bufH;   // 8 uint4 per node row
    float acc[8];
    {
        uint4 hv = hp[v * 8 + c];             // self-loop term
        float2 f0 = __half22float2(*(const __half2*)&hv.x);
        float2 f1 = __half22float2(*(const __half2*)&hv.y);
        float2 f2 = __half22float2(*(const __half2*)&hv.z);
        float2 f3 = __half22float2(*(const __half2*)&hv.w);
        acc[0] = f0.x; acc[1] = f0.y; acc[2] = f1.x; acc[3] = f1.y;
        acc[4] = f2.x; acc[5] = f2.y; acc[6] = f3.x; acc[7] = f3.y;
    }
    int e = g_off[v], e1 = g_off[v + 1];
#pragma unroll 4
    for (; e < e1; e++) {
        int s = __ldg(&g_srcs[e]);
        uint4 hv = __ldg(&hp[s * 8 + c]);
        float2 f0 = __half22float2(*(const __half2*)&hv.x);
        float2 f1 = __half22float2(*(const __half2*)&hv.y);
        float2 f2 = __half22float2(*(const __half2*)&hv.z);
        float2 f3 = __half22float2(*(const __half2*)&hv.w);
        acc[0] += f0.x; acc[1] += f0.y; acc[2] += f1.x; acc[3] += f1.y;
        acc[4] += f2.x; acc[5] += f2.y; acc[6] += f3.x; acc[7] += f3.y;
    }
    float dv = g_dinv[v];
    float4 bb0 = ((const float4*)b3)[2 * c];
    float4 bb1 = ((const float4*)b3)[2 * c + 1];
    float h[8];
    h[0] = fmaxf(fmaf(acc[0], dv, bb0.x), 0.f);
    h[1] = fmaxf(fmaf(acc[1], dv, bb0.y), 0.f);
    h[2] = fmaxf(fmaf(acc[2], dv, bb0.z), 0.f);
    h[3] = fmaxf(fmaf(acc[3], dv, bb0.w), 0.f);
    h[4] = fmaxf(fmaf(acc[4], dv, bb1.x), 0.f);
    h[5] = fmaxf(fmaf(acc[5], dv, bb1.y), 0.f);
    h[6] = fmaxf(fmaf(acc[6], dv, bb1.z), 0.f);
    h[7] = fmaxf(fmaf(acc[7], dv, bb1.w), 0.f);
    const float* w = &sW4[c * 8 * 5];
    float p[5];
#pragma unroll
    for (int j = 0; j < 5; j++) {
        float s = h[0] * w[j];
#pragma unroll
        for (int i = 1; i < 8; i++) s = fmaf(h[i], w[i * 5 + j], s);
        p[j] = s;
    }
    unsigned m = __activemask();
#pragma unroll
    for (int off = 4; off > 0; off >>= 1) {
#pragma unroll
        for (int j = 0; j < 5; j++) p[j] += __shfl_down_sync(m, p[j], off, 8);
    }
    if (c == 0) {
        g_bufB[v * 2 + 0] = make_float4(dv * p[0], dv * p[1], dv * p[2], dv * p[3]);
        g_bufB[v * 2 + 1] = make_float4(dv * p[4], 0.f, 0.f, 0.f);
    }
}

// ---------------- final d=5 agg + b4 + log_softmax ----------------
__global__ void k_final(const float* __restrict__ b4, float* __restrict__ out, int n) {
    int v = blockIdx.x * blockDim.x + threadIdx.x;
    if (v >= n) return;
    float4 a0 = g_bufB[v * 2 + 0];
    float4 a1 = g_bufB[v * 2 + 1];
    int e = g_off[v], e1 = g_off[v + 1];
#pragma unroll 4
    for (; e < e1; e++) {
        int s = __ldg(&g_srcs[e]);
        float4 t0 = __ldg(&g_bufB[s * 2 + 0]);
        float4 t1 = __ldg(&g_bufB[s * 2 + 1]);
        a0.x += t0.x; a0.y += t0.y; a0.z += t0.z; a0.w += t0.w;
        a1.x += t1.x;
    }
    float dv = g_dinv[v];
    float z[5];
    z[0] = fmaf(a0.x, dv, b4[0]);
    z[1] = fmaf(a0.y, dv, b4[1]);
    z[2] = fmaf(a0.z, dv, b4[2]);
    z[3] = fmaf(a0.w, dv, b4[3]);
    z[4] = fmaf(a1.x, dv, b4[4]);
    float mx = z[0];
#pragma unroll
    for (int j = 1; j < 5; j++) mx = fmaxf(mx, z[j]);
    float sum = 0.f;
#pragma unroll
    for (int j = 0; j < 5; j++) sum += expf(z[j] - mx);
    float l = mx + logf(sum);
#pragma unroll
    for (int j = 0; j < 5; j++) out[v * 5 + j] = z[j] - l;
}

extern "C" void kernel_launch(void* const* d_in, const int* in_sizes, int n_in,
                              void* d_out, int out_size) {
    const float* x  = (const float*)d_in[0];
    const int*   ei = (const int*)d_in[1];      // int32 (JAX x64 disabled)
    const float* W1 = (const float*)d_in[2];
    const float* b1 = (const float*)d_in[3];
    const float* W2 = (const float*)d_in[4];
    const float* b2 = (const float*)d_in[5];
    const float* W3 = (const float*)d_in[6];
    const float* b3 = (const float*)d_in[7];
    const float* W4 = (const float*)d_in[8];
    const float* b4 = (const float*)d_in[9];
    float* out = (float*)d_out;

    int N = in_sizes[0];
    int E = in_sizes[1] / 2;

    int nB  = (N + 255) / 256;
    int snb = (N + SCAN_TPB - 1) / SCAN_TPB;

    // CSR build
    k_zero<<<nB, 256>>>(N);
    if ((E & 3) == 0) {
        int E4 = E >> 2;
        int eB4 = (E4 + 255) / 256;
        k_count4<<<eB4, 256>>>(ei + E, E4);
        k_scan1<<<snb, SCAN_TPB>>>(N);
        k_scan2<<<1, 256>>>(snb);
        k_scan3<<<nB, 256>>>(x, N, E);
        k_fill4<<<eB4, 256>>>(ei, E, E4);
    } else {
        int eB = (E + 255) / 256;
        k_count<<<eB, 256>>>(ei, E);
        k_scan1<<<snb, SCAN_TPB>>>(N);
        k_scan2<<<1, 256>>>(snb);
        k_scan3<<<nB, 256>>>(x, N, E);
        k_fill<<<eB, 256>>>(ei, E);
    }

    // Layer 1: scalar agg + transform (1->16), fp16 out
    k_l1<<<nB, 256>>>(W1, b1, N);
    // Layer 2 agg in d=16 fp16 (before W2)
    k_agg2<<<(N * 2 + 255) / 256, 256>>>(N);
    // Fused W2+relu+W3 node transform (fp16 output)
    k_t23<<<(N + 127) / 128, 128>>>(W2, b2, W3, N);
    // Layer 3 agg d=64 fp16, fused bias/relu/W4 epilogue
    k_agg3w4<<<(N * 8 + 255) / 256, 256>>>(b3, W4, N);
    // Layer 4 agg d=5 + log_softmax
    k_final<<<nB, 256>>>(b4, out, N);
}